// round 11
// baseline (speedup 1.0000x reference)
#include <cuda_runtime.h>
#include <stdint.h>

#define Bn 4096
#define Dn 16
#define Mn 4
#define Rn 2048
#define Cn 10
#define BT 32
#define WARPS 32
#define THREADS 1024
#define RPW 64          // rules per warp
#define CHUNK 4
#define SSTRIDE 40      // banks 8j+row: conflict-free STS and transposed LDS
#define EPSV 1e-9f

// scratch (module-load allocation, allowed)
__device__ uint4 g_offp[Rn];          // packed u16 table byte-offsets (5 per rule)
__device__ float g_cs[Rn * 12];       // folded consequents (+1.0 fsum slot, 0 pad)

__device__ __forceinline__ void ffma2(unsigned long long& acc,
                                      unsigned long long a,
                                      unsigned long long b) {
    asm("fma.rn.f32x2 %0, %1, %2, %0;" : "+l"(acc) : "l"(a), "l"(b));
}
__device__ __forceinline__ unsigned long long bcast2(float f) {
    unsigned long long r;
    asm("mov.b64 %0, {%1, %1};" : "=l"(r) : "f"(f));
    return r;
}

// ---------------------------------------------------------------------------
// prep: 8 rules per 256-thread CTA, smem-staged
// ---------------------------------------------------------------------------
__global__ void anfis_prep(const float* __restrict__ cons,
                           const int*   __restrict__ rules) {
    __shared__ float s[8 * 170];
    const int r0 = blockIdx.x * 8;
    const float* base = cons + (size_t)r0 * 170;
    for (int i = threadIdx.x; i < 8 * 170; i += 256) s[i] = base[i];
    __syncthreads();
    const int t = threadIdx.x;
    if (t < 80) {
        int rr = t / 10, c = t % 10;
        float a = 0.f;
#pragma unroll
        for (int j = 0; j < 17; j++) a += s[rr * 170 + j * 10 + c];
        g_cs[(size_t)(r0 + rr) * 12 + c] = a;
    } else if (t < 96) {
        int rr = (t - 80) >> 1;
        // slot [10] = 1.0 -> fsum rides the FFMA2 stream; [11] = 0
        g_cs[(size_t)(r0 + rr) * 12 + 10 + ((t - 80) & 1)] =
            ((t - 80) & 1) ? 0.f : 1.f;
    } else if (t < 104) {
        int rr = t - 96;
        const int* rp = rules + (size_t)(r0 + rr) * Dn;
        // groups: (0-2),(3-5),(6-8),(9-11) -> 64 entries; (12-15) -> 256
        uint32_t i0 = ((uint32_t)rp[0] & 3u) | (((uint32_t)rp[1] & 3u) << 2)
                    | (((uint32_t)rp[2] & 3u) << 4);
        uint32_t i1 = ((uint32_t)rp[3] & 3u) | (((uint32_t)rp[4] & 3u) << 2)
                    | (((uint32_t)rp[5] & 3u) << 4);
        uint32_t i2 = ((uint32_t)rp[6] & 3u) | (((uint32_t)rp[7] & 3u) << 2)
                    | (((uint32_t)rp[8] & 3u) << 4);
        uint32_t i3 = ((uint32_t)rp[9] & 3u) | (((uint32_t)rp[10] & 3u) << 2)
                    | (((uint32_t)rp[11] & 3u) << 4);
        uint32_t i4 = ((uint32_t)rp[12] & 3u) | (((uint32_t)rp[13] & 3u) << 2)
                    | (((uint32_t)rp[14] & 3u) << 4) | (((uint32_t)rp[15] & 3u) << 6);
        uint32_t o0 =            i0 * 128u;
        uint32_t o1 =  8192u  +  i1 * 128u;
        uint32_t o2 =  16384u +  i2 * 128u;
        uint32_t o3 =  24576u +  i3 * 128u;
        uint32_t o4 =  32768u +  i4 * 128u;          // <= 65408, fits u16
        uint4 o;
        o.x = o0 | (o1 << 16);
        o.y = o2 | (o3 << 16);
        o.z = o4;
        o.w = 0;
        g_offp[r0 + rr] = o;
    }
}

// ---------------------------------------------------------------------------
// main: one 1024-thread CTA per 32-row batch tile, all 2048 rules.
// All-smem rule loop (zero LDG), 32 warps to saturate the LDS crossbar.
// ---------------------------------------------------------------------------
// smem floats: tbl 512*32=16384 | stage 32*4*40=5120 (overlays mf 2048 +
//   pair 1024 at build) | csm 2048*12=24576 | soff 2048*4=8192 |
//   xs 512 | red 384 | inv 32  => 55200 floats = 220800 B < 227KB
#define STAGE_FLOATS (WARPS * CHUNK * SSTRIDE)
#define SMEM_FLOATS  (16384 + STAGE_FLOATS + 24576 + 8192 + 512 + 384 + 32)
#define SMEM_BYTES   (SMEM_FLOATS * 4)

__global__ void __launch_bounds__(THREADS, 1)
anfis_main(const float* __restrict__ x,
           const float* __restrict__ centers,
           const float* __restrict__ widths,
           float* __restrict__ out,     // (B, C)
           float* __restrict__ nf,      // (B, R)
           float* __restrict__ xext,    // (B, D+1)
           int write_aux) {
    extern __shared__ float sm[];
    float* tbl   = sm;                      // 512*32
    float* stage = tbl + 16384;             // 32*4*40
    float* csm   = stage + STAGE_FLOATS;    // 2048*12
    uint4* soff  = (uint4*)(csm + 24576);   // 2048
    float* xs    = (float*)(soff + 2048);   // 32*16
    float* red   = xs + 512;                // 12*32
    float* inv_s = red + 384;               // 32
    float* mf    = stage;                   // overlay (build only) 64*32
    float* pair  = stage + 2048;            // overlay (build only) 32*32

    const int tid  = threadIdx.x;
    const int w    = tid >> 5;
    const int lane = tid & 31;
    const int b0   = blockIdx.x * BT;

    // ---- build phase ----
    if (tid < BT * Dn)
        xs[tid] = x[(size_t)b0 * Dn + tid];
    if (tid < 384) red[tid] = 0.f;

    // stage consequents + offsets into smem (coalesced, wide)
    {
        const float4* src = (const float4*)g_cs;
        float4* dst = (float4*)csm;
#pragma unroll
        for (int k = 0; k < 6; k++)
            dst[tid + k * THREADS] = src[tid + k * THREADS];   // 6144 float4
#pragma unroll
        for (int k = 0; k < 2; k++)
            soff[tid + k * THREADS] = g_offp[tid + k * THREADS];
    }
    __syncthreads();

    // membership values: 2048 entries, 2 iterations x 1024 threads
#pragma unroll
    for (int e = tid; e < 64 * 32; e += THREADS) {
        int dm = e >> 5, b = e & 31;
        int d = dm >> 2, m = dm & 3;
        float cc = centers[d * Mn + m];
        float ww = widths[d * Mn + m];
        float df = xs[b * Dn + d] - cc;
        mf[dm * 32 + b] = expf(-df * df / (2.f * ww * ww));
    }
    __syncthreads();

    // groups 0-3: 3 dims each, 64 entries
    for (int pp = w; pp < 256; pp += WARPS) {
        int g = pp >> 6, idx = pp & 63;
        tbl[pp * 32 + lane] =
            mf[((3*g + 0) * 4 + ( idx       & 3)) * 32 + lane] *
            mf[((3*g + 1) * 4 + ((idx >> 2) & 3)) * 32 + lane] *
            mf[((3*g + 2) * 4 + ( idx >> 4     )) * 32 + lane];
    }
    // pair tables for group 4 (dims 12-13, 14-15)
    for (int pp = w; pp < 32; pp += WARPS) {
        int grp = pp >> 4, i2 = pp & 15;
        int d0 = 12 + grp * 2;
        pair[pp * 32 + lane] =
            mf[(d0     * 4 + (i2 & 3))  * 32 + lane] *
            mf[((d0+1) * 4 + (i2 >> 2)) * 32 + lane];
    }
    __syncthreads();
    // group 4: 4 dims, 256 entries
    for (int pp = w; pp < 256; pp += WARPS) {
        tbl[(256 + pp) * 32 + lane] =
            pair[(pp & 15) * 32 + lane] * pair[(16 + (pp >> 4)) * 32 + lane];
    }
    __syncthreads();   // stage region free from here

    // ---- main loop: 64 rules/warp in chunks of 4, all-smem ----
    const char* tb = (const char*)tbl + lane * 4;
    const ulonglong2* cs2 = (const ulonglong2*)csm;
    const int rbase = w * RPW;
    float* stg = stage + w * (CHUNK * SSTRIDE);

    unsigned long long a01 = 0, a23 = 0, a45 = 0, a67 = 0, a89 = 0, aSF = 0;

    for (int ch = 0; ch < RPW / CHUNK; ch++) {
        const int r0 = rbase + ch * CHUNK;
#pragma unroll
        for (int rl = 0; rl < CHUNK; rl++) {
            const int r = r0 + rl;
            const uint4 o = soff[r];                       // LDS.128 broadcast
            float f0 = *(const float*)(tb + (o.x & 0xFFFFu));
            float f1 = *(const float*)(tb + (o.x >> 16));
            float f2 = *(const float*)(tb + (o.y & 0xFFFFu));
            float f3 = *(const float*)(tb + (o.y >> 16));
            float f4 = *(const float*)(tb + o.z);
            float f = ((f0 * f1) * (f2 * f3)) * f4;
            stg[rl * SSTRIDE + lane] = f;
            unsigned long long fp = bcast2(f);
            ulonglong2 v0 = cs2[r * 3 + 0];                // LDS.128 broadcast
            ulonglong2 v1 = cs2[r * 3 + 1];
            ulonglong2 v2 = cs2[r * 3 + 2];
            ffma2(a01, fp, v0.x); ffma2(a23, fp, v0.y);
            ffma2(a45, fp, v1.x); ffma2(a67, fp, v1.y);
            ffma2(a89, fp, v2.x); ffma2(aSF, fp, v2.y);    // .lo = fsum
        }
        __syncwarp();
        if (write_aux) {
            // transposed flush: 8 rows x 4 rules per iter, banks (8j+row)%32
#pragma unroll
            for (int t2 = 0; t2 < 4; t2++) {
                int row = 8 * t2 + (lane >> 2);   // batch row
                int j = lane & 3;                 // rule-in-chunk
                nf[(size_t)(b0 + row) * Rn + r0 + j] = stg[j * SSTRIDE + row];
            }
        }
        __syncwarp();
    }

    // ---- CTA reduction (smem atomics, one-time) ----
    {
        union { unsigned long long u; float2 f; } c0, c1, c2, c3, c4, c5;
        c0.u = a01; c1.u = a23; c2.u = a45; c3.u = a67; c4.u = a89; c5.u = aSF;
        atomicAdd(&red[ 0 * 32 + lane], c0.f.x);
        atomicAdd(&red[ 1 * 32 + lane], c0.f.y);
        atomicAdd(&red[ 2 * 32 + lane], c1.f.x);
        atomicAdd(&red[ 3 * 32 + lane], c1.f.y);
        atomicAdd(&red[ 4 * 32 + lane], c2.f.x);
        atomicAdd(&red[ 5 * 32 + lane], c2.f.y);
        atomicAdd(&red[ 6 * 32 + lane], c3.f.x);
        atomicAdd(&red[ 7 * 32 + lane], c3.f.y);
        atomicAdd(&red[ 8 * 32 + lane], c4.f.x);
        atomicAdd(&red[ 9 * 32 + lane], c4.f.y);
        atomicAdd(&red[10 * 32 + lane], c5.f.x);
    }
    __syncthreads();

    if (tid < 32)
        inv_s[tid] = 1.f / (red[10 * 32 + tid] + EPSV);
    __syncthreads();

    // out[b][c] = sx[b] * inv[b] * acc[b][c]
    if (tid < BT * Cn) {
        int b = tid & 31, c = tid >> 5;
        float s = 1.f;
#pragma unroll
        for (int d = 0; d < Dn; d++) s += xs[b * Dn + d];
        out[(size_t)(b0 + b) * Cn + c] = s * inv_s[b] * red[c * 32 + b];
    }

    if (write_aux) {
        if (tid < BT * (Dn + 1)) {
            int b = tid / (Dn + 1), j = tid % (Dn + 1);
            xext[(size_t)(b0 + b) * (Dn + 1) + j] =
                (j < Dn) ? xs[b * Dn + j] : 1.f;
        }
        // in-place normalize of this CTA's nf region (L2-resident), float4
        __syncthreads();
        float4* p = (float4*)(nf + (size_t)b0 * Rn);
#pragma unroll
        for (int k = 0; k < 16; k++) {
            int i = tid + k * THREADS;          // 16384 float4 = 32 rows x 512
            float iv = inv_s[i >> 9];           // Rn/4 = 512 float4 per row
            float4 v = p[i];
            v.x *= iv; v.y *= iv; v.z *= iv; v.w *= iv;
            p[i] = v;
        }
    }
}

// ---------------------------------------------------------------------------
extern "C" void kernel_launch(void* const* d_in, const int* in_sizes, int n_in,
                              void* d_out, int out_size) {
    const float* x       = (const float*)d_in[0];
    const float* centers = (const float*)d_in[1];
    const float* widths  = (const float*)d_in[2];
    const float* cons    = (const float*)d_in[3];
    const int*   rules   = (const int*)d_in[4];

    float* out = (float*)d_out;
    const long total = (long)Bn * Cn + (long)Bn * Rn + (long)Bn * (Dn + 1);
    const int write_aux = (out_size >= total) ? 1 : 0;
    float* nf   = out + (size_t)Bn * Cn;
    float* xext = nf + (size_t)Bn * Rn;

    anfis_prep<<<Rn / 8, 256>>>(cons, rules);

    cudaFuncSetAttribute(anfis_main, cudaFuncAttributeMaxDynamicSharedMemorySize,
                         SMEM_BYTES);
    anfis_main<<<Bn / BT, THREADS, SMEM_BYTES>>>(x, centers, widths,
                                                 out, nf, xext, write_aux);
}

// round 12
// speedup vs baseline: 1.0564x; 1.0564x over previous
#include <cuda_runtime.h>
#include <stdint.h>

#define Bn 4096
#define Dn 16
#define Mn 4
#define Rn 2048
#define Cn 10
#define BT 32
#define WARPS 16
#define THREADS 512
#define RPW 128         // rules per warp
#define CHUNK 32
#define SSTRIDE 33      // banks (lane+rr)%32: conflict-free both directions
#define EPSV 1e-9f

// scratch (module-load allocation, allowed)
__device__ uint2 g_sidx[Rn];          // 4 packed u16 table entry-indices per rule
__device__ float g_cs[Rn * 12];       // folded consequents, 3 x float4 per rule

// ---------------------------------------------------------------------------
// prep: 8 rules per 256-thread CTA, smem-staged
// ---------------------------------------------------------------------------
__global__ void anfis_prep(const float* __restrict__ cons,
                           const int*   __restrict__ rules) {
    __shared__ float s[8 * 170];
    const int r0 = blockIdx.x * 8;
    const float* base = cons + (size_t)r0 * 170;
    for (int i = threadIdx.x; i < 8 * 170; i += 256) s[i] = base[i];
    __syncthreads();
    const int t = threadIdx.x;
    if (t < 80) {
        int rr = t / 10, c = t % 10;
        float a = 0.f;
#pragma unroll
        for (int j = 0; j < 17; j++) a += s[rr * 170 + j * 10 + c];
        g_cs[(size_t)(r0 + rr) * 12 + c] = a;
    } else if (t < 96) {
        int rr = (t - 80) >> 1;
        g_cs[(size_t)(r0 + rr) * 12 + 10 + ((t - 80) & 1)] = 0.f;  // pad
    } else if (t < 104) {
        int rr = t - 96;
        const int* rp = rules + (size_t)(r0 + rr) * Dn;
        // 4 groups of 4 dims -> 8-bit combo each; entry = g*256 + combo
        uint32_t ix[4];
#pragma unroll
        for (int g = 0; g < 4; g++)
            ix[g] = ((uint32_t)rp[4*g]   & 3u)
                  | (((uint32_t)rp[4*g+1] & 3u) << 2)
                  | (((uint32_t)rp[4*g+2] & 3u) << 4)
                  | (((uint32_t)rp[4*g+3] & 3u) << 6);
        uint2 oo;
        oo.x = (ix[0])          | ((256u + ix[1]) << 16);
        oo.y = (512u + ix[2])   | ((768u + ix[3]) << 16);
        g_sidx[r0 + rr] = oo;
    }
}

// ---------------------------------------------------------------------------
// main: one 512-thread CTA per 32-row batch tile, all 2048 rules.
// 1024-entry table (4 lookups), cs via uniform LDG, CHUNK=32 coalesced flush.
// ---------------------------------------------------------------------------
// smem floats: tbl 1024*32=32768 | stage 16*32*33=16896 (overlays mf 2048 +
//   pair 4096 at build) | soff 2048*uint2=4096 | xs 512 | red 384 | inv 32
#define STAGE_FLOATS (WARPS * CHUNK * SSTRIDE)
#define SMEM_FLOATS  (32768 + STAGE_FLOATS + 4096 + 512 + 384 + 32)
#define SMEM_BYTES   (SMEM_FLOATS * 4)    // 218,752 B

__global__ void __launch_bounds__(THREADS, 1)
anfis_main(const float* __restrict__ x,
           const float* __restrict__ centers,
           const float* __restrict__ widths,
           float* __restrict__ out,     // (B, C)
           float* __restrict__ nf,      // (B, R)
           float* __restrict__ xext,    // (B, D+1)
           int write_aux) {
    extern __shared__ float sm[];
    float* tbl   = sm;                      // 1024*32
    float* stage = tbl + 32768;             // 16*32*33
    uint2* soff  = (uint2*)(stage + STAGE_FLOATS);   // 2048 uint2
    float* xs    = (float*)(soff + 2048);   // 32*16
    float* red   = xs + 512;                // 12*32
    float* inv_s = red + 384;               // 32
    float* mf    = stage;                   // overlay (build only) 64*32
    float* pair  = stage + 2048;            // overlay (build only) 128*32

    const int tid  = threadIdx.x;
    const int w    = tid >> 5;
    const int lane = tid & 31;
    const int b0   = blockIdx.x * BT;

    // ---- build phase ----
    if (tid < BT * Dn)
        xs[tid] = x[(size_t)b0 * Dn + tid];
    if (tid < 384) red[tid] = 0.f;

    // stage rule entry-indices into smem (coalesced)
#pragma unroll
    for (int k = 0; k < 4; k++)
        soff[tid + k * THREADS] = g_sidx[tid + k * THREADS];
    __syncthreads();

    // membership values
#pragma unroll
    for (int e = tid; e < 64 * 32; e += THREADS) {
        int dm = e >> 5, b = e & 31;
        int d = dm >> 2, m = dm & 3;
        float cc = centers[d * Mn + m];
        float ww = widths[d * Mn + m];
        float df = xs[b * Dn + d] - cc;
        mf[dm * 32 + b] = expf(-df * df / (2.f * ww * ww));
    }
    __syncthreads();

    // pair tables: 8 dim-pairs x 16 combos
    for (int pp = w; pp < 128; pp += WARPS) {
        int pr = pp >> 4, i2 = pp & 15;
        pair[pp * 32 + lane] =
            mf[((2 * pr)     * 4 + (i2 & 3))  * 32 + lane] *
            mf[((2 * pr + 1) * 4 + (i2 >> 2)) * 32 + lane];
    }
    __syncthreads();

    // 4-dim group tables: 4 groups x 256 entries (1024 total)
    for (int pp = w; pp < 1024; pp += WARPS) {
        int g = pp >> 8, idx = pp & 255;
        tbl[pp * 32 + lane] =
            pair[((2 * g)     * 16 + (idx & 15)) * 32 + lane] *
            pair[((2 * g + 1) * 16 + (idx >> 4)) * 32 + lane];
    }
    __syncthreads();   // stage region free from here

    // ---- main loop: 128 rules/warp in chunks of 32 ----
    const char* tbB = (const char*)tbl + lane * 4;
    const int rbase = w * RPW;
    float* stg = stage + w * (CHUNK * SSTRIDE);

    float a0 = 0.f, a1 = 0.f, a2 = 0.f, a3 = 0.f, a4 = 0.f;
    float a5 = 0.f, a6 = 0.f, a7 = 0.f, a8 = 0.f, a9 = 0.f;
    float fsum = 0.f;

    for (int ch = 0; ch < RPW / CHUNK; ch++) {
        const int r0 = rbase + ch * CHUNK;
#pragma unroll 8
        for (int rl = 0; rl < CHUNK; rl++) {
            const int r = r0 + rl;
            const uint2 oo = soff[r];                  // LDS.64 broadcast
            uint32_t e0 = (oo.x & 0xFFFFu) << 7;
            uint32_t e1 = (oo.x >> 16)     << 7;
            uint32_t e2 = (oo.y & 0xFFFFu) << 7;
            uint32_t e3 = (oo.y >> 16)     << 7;
            float f0 = *(const float*)(tbB + e0);
            float f1 = *(const float*)(tbB + e1);
            float f2 = *(const float*)(tbB + e2);
            float f3 = *(const float*)(tbB + e3);
            float f = (f0 * f1) * (f2 * f3);
            stg[rl * SSTRIDE + lane] = f;
            fsum += f;
            // uniform LDG.128 x3 (L2-resident, 1 line each)
            const float4* gc = (const float4*)(g_cs + (size_t)r * 12);
            float4 c0 = gc[0];
            float4 c1 = gc[1];
            float4 c2 = gc[2];
            a0 += f * c0.x; a1 += f * c0.y; a2 += f * c0.z; a3 += f * c0.w;
            a4 += f * c1.x; a5 += f * c1.y; a6 += f * c1.z; a7 += f * c1.w;
            a8 += f * c2.x; a9 += f * c2.y;
        }
        __syncwarp();
        if (write_aux) {
            // transposed flush: 128B fully-coalesced rows, banks (lane+rr)%32
#pragma unroll 8
            for (int rr = 0; rr < CHUNK; rr++)
                nf[(size_t)(b0 + rr) * Rn + r0 + lane] = stg[lane * SSTRIDE + rr];
        }
        __syncwarp();
    }

    // ---- CTA reduction (smem atomics, one-time) ----
    atomicAdd(&red[ 0 * 32 + lane], a0);
    atomicAdd(&red[ 1 * 32 + lane], a1);
    atomicAdd(&red[ 2 * 32 + lane], a2);
    atomicAdd(&red[ 3 * 32 + lane], a3);
    atomicAdd(&red[ 4 * 32 + lane], a4);
    atomicAdd(&red[ 5 * 32 + lane], a5);
    atomicAdd(&red[ 6 * 32 + lane], a6);
    atomicAdd(&red[ 7 * 32 + lane], a7);
    atomicAdd(&red[ 8 * 32 + lane], a8);
    atomicAdd(&red[ 9 * 32 + lane], a9);
    atomicAdd(&red[10 * 32 + lane], fsum);
    __syncthreads();

    if (tid < 32)
        inv_s[tid] = 1.f / (red[10 * 32 + tid] + EPSV);
    __syncthreads();

    // out[b][c] = sx[b] * inv[b] * acc[b][c]
    if (tid < BT * Cn) {
        int b = tid & 31, c = tid >> 5;
        float s = 1.f;
#pragma unroll
        for (int d = 0; d < Dn; d++) s += xs[b * Dn + d];
        out[(size_t)(b0 + b) * Cn + c] = s * inv_s[b] * red[c * 32 + b];
    }

    if (write_aux) {
        for (int i = tid; i < BT * (Dn + 1); i += THREADS) {
            int b = i / (Dn + 1), j = i % (Dn + 1);
            xext[(size_t)(b0 + b) * (Dn + 1) + j] =
                (j < Dn) ? xs[b * Dn + j] : 1.f;
        }
        // in-place normalize of this CTA's nf region (L2-resident), float4
        __syncthreads();
        float4* p = (float4*)(nf + (size_t)b0 * Rn);
#pragma unroll
        for (int k = 0; k < 32; k++) {
            int i = tid + k * THREADS;          // 16384 float4 = 32 rows x 512
            float iv = inv_s[i >> 9];           // Rn/4 = 512 float4 per row
            float4 v = p[i];
            v.x *= iv; v.y *= iv; v.z *= iv; v.w *= iv;
            p[i] = v;
        }
    }
}

// ---------------------------------------------------------------------------
extern "C" void kernel_launch(void* const* d_in, const int* in_sizes, int n_in,
                              void* d_out, int out_size) {
    const float* x       = (const float*)d_in[0];
    const float* centers = (const float*)d_in[1];
    const float* widths  = (const float*)d_in[2];
    const float* cons    = (const float*)d_in[3];
    const int*   rules   = (const int*)d_in[4];

    float* out = (float*)d_out;
    const long total = (long)Bn * Cn + (long)Bn * Rn + (long)Bn * (Dn + 1);
    const int write_aux = (out_size >= total) ? 1 : 0;
    float* nf   = out + (size_t)Bn * Cn;
    float* xext = nf + (size_t)Bn * Rn;

    anfis_prep<<<Rn / 8, 256>>>(cons, rules);

    cudaFuncSetAttribute(anfis_main, cudaFuncAttributeMaxDynamicSharedMemorySize,
                         SMEM_BYTES);
    anfis_main<<<Bn / BT, THREADS, SMEM_BYTES>>>(x, centers, widths,
                                                 out, nf, xext, write_aux);
}

// round 14
// speedup vs baseline: 1.1654x; 1.1032x over previous
#include <cuda_runtime.h>
#include <stdint.h>

#define Bn 4096
#define Dn 16
#define Mn 4
#define Rn 2048
#define Cn 10
#define BT 32
#define WARPS 16
#define THREADS 512
#define RPW 128         // rules per warp
#define CHUNK 16
#define SSTRIDE 33
#define EPSV 1e-9f

// scratch (module-load allocation, allowed)
__device__ uint2          g_sidx2[Rn];   // pre-scaled u16 offsets o0|o1, o2|o3
__device__ unsigned short g_s4[Rn];      // pre-scaled u16 offset o4
__device__ float          g_cs[Rn * 12]; // folded consequents (+1.0 fsum, 0 pad)

__device__ __forceinline__ void ffma2(unsigned long long& acc,
                                      unsigned long long a,
                                      unsigned long long b) {
    asm("fma.rn.f32x2 %0, %1, %2, %0;" : "+l"(acc) : "l"(a), "l"(b));
}
__device__ __forceinline__ unsigned long long bcast2(float f) {
    unsigned long long r;
    asm("mov.b64 %0, {%1, %1};" : "=l"(r) : "f"(f));
    return r;
}

// ---------------------------------------------------------------------------
// prep: 8 rules per 256-thread CTA, smem-staged
// ---------------------------------------------------------------------------
__global__ void anfis_prep(const float* __restrict__ cons,
                           const int*   __restrict__ rules) {
    __shared__ float s[8 * 170];
    const int r0 = blockIdx.x * 8;
    const float* base = cons + (size_t)r0 * 170;
    for (int i = threadIdx.x; i < 8 * 170; i += 256) s[i] = base[i];
    __syncthreads();
    const int t = threadIdx.x;
    if (t < 80) {
        int rr = t / 10, c = t % 10;
        float a = 0.f;
#pragma unroll
        for (int j = 0; j < 17; j++) a += s[rr * 170 + j * 10 + c];
        g_cs[(size_t)(r0 + rr) * 12 + c] = a;
    } else if (t < 96) {
        int rr = (t - 80) >> 1;
        // slot [10] = 1.0 -> fsum rides the FFMA2 stream; [11] = 0
        g_cs[(size_t)(r0 + rr) * 12 + 10 + ((t - 80) & 1)] =
            ((t - 80) & 1) ? 0.f : 1.f;
    } else if (t < 104) {
        int rr = t - 96;
        const int* rp = rules + (size_t)(r0 + rr) * Dn;
        // groups: (0-2),(3-5),(6-8),(9-11) -> 64 entries; (12-15) -> 256
        uint32_t i0 = ((uint32_t)rp[0] & 3u) | (((uint32_t)rp[1] & 3u) << 2)
                    | (((uint32_t)rp[2] & 3u) << 4);
        uint32_t i1 = ((uint32_t)rp[3] & 3u) | (((uint32_t)rp[4] & 3u) << 2)
                    | (((uint32_t)rp[5] & 3u) << 4);
        uint32_t i2 = ((uint32_t)rp[6] & 3u) | (((uint32_t)rp[7] & 3u) << 2)
                    | (((uint32_t)rp[8] & 3u) << 4);
        uint32_t i3 = ((uint32_t)rp[9] & 3u) | (((uint32_t)rp[10] & 3u) << 2)
                    | (((uint32_t)rp[11] & 3u) << 4);
        uint32_t i4 = ((uint32_t)rp[12] & 3u) | (((uint32_t)rp[13] & 3u) << 2)
                    | (((uint32_t)rp[14] & 3u) << 4) | (((uint32_t)rp[15] & 3u) << 6);
        uint32_t o0 =           i0 * 128u;           // <= 8064
        uint32_t o1 = ( 64u  + i1) * 128u;           // <= 16256
        uint32_t o2 = (128u  + i2) * 128u;           // <= 24448
        uint32_t o3 = (192u  + i3) * 128u;           // <= 32640
        uint32_t o4 = (256u  + i4) * 128u;           // <= 65408, fits u16
        uint2 oa;
        oa.x = o0 | (o1 << 16);
        oa.y = o2 | (o3 << 16);
        g_sidx2[r0 + rr] = oa;
        g_s4[r0 + rr] = (unsigned short)o4;
    }
}

// ---------------------------------------------------------------------------
// main: one 512-thread CTA per 32-row batch tile, all 2048 rules.
// All-smem rule loop; pre-scaled u16 offsets; CHUNK 16 coalesced flush.
// ---------------------------------------------------------------------------
// smem floats: tbl 512*32=16384 | stage 16*16*33=8448 (overlays mf 2048 +
//   pair 1024 at build) | csm 2048*12=24576 | sofA 4096 | sofB 1024 |
//   xs 512 | red 384 | inv 32   => 55456 floats = 221824 B < 227 KB
#define STAGE_FLOATS (WARPS * CHUNK * SSTRIDE)
#define SMEM_FLOATS  (16384 + STAGE_FLOATS + 24576 + 4096 + 1024 + 512 + 384 + 32)
#define SMEM_BYTES   (SMEM_FLOATS * 4)

__global__ void __launch_bounds__(THREADS, 1)
anfis_main(const float* __restrict__ x,
           const float* __restrict__ centers,
           const float* __restrict__ widths,
           float* __restrict__ out,     // (B, C)
           float* __restrict__ nf,      // (B, R)
           float* __restrict__ xext,    // (B, D+1)
           int write_aux) {
    extern __shared__ float sm[];
    float* tbl   = sm;                              // 512*32
    float* stage = tbl + 16384;                     // 16*16*33
    float* csm   = stage + STAGE_FLOATS;            // 2048*12 (16B aligned)
    uint2* sofA  = (uint2*)(csm + 24576);           // 2048 uint2
    unsigned short* sofB = (unsigned short*)(sofA + 2048);  // 2048 u16
    float* xs    = (float*)(sofB + 2048);           // 32*16
    float* red   = xs + 512;                        // 12*32
    float* inv_s = red + 384;                       // 32
    float* mf    = stage;                           // overlay (build) 64*32
    float* pair  = stage + 2048;                    // overlay (build) 32*32

    const int tid  = threadIdx.x;
    const int w    = tid >> 5;
    const int lane = tid & 31;
    const int b0   = blockIdx.x * BT;

    // ---- build phase ----
    if (tid < BT * Dn)
        xs[tid] = x[(size_t)b0 * Dn + tid];
    if (tid < 384) red[tid] = 0.f;

    // stage consequents + offsets into smem (coalesced, wide)
    {
        const float4* src = (const float4*)g_cs;
        float4* dst = (float4*)csm;
#pragma unroll
        for (int k = 0; k < 12; k++)
            dst[tid + k * THREADS] = src[tid + k * THREADS];   // 6144 float4
#pragma unroll
        for (int k = 0; k < 4; k++)
            sofA[tid + k * THREADS] = g_sidx2[tid + k * THREADS];
        const uint32_t* s4src = (const uint32_t*)g_s4;
        uint32_t* s4dst = (uint32_t*)sofB;
#pragma unroll
        for (int k = 0; k < 2; k++)
            s4dst[tid + k * THREADS] = s4src[tid + k * THREADS];
    }
    __syncthreads();

    // membership values
#pragma unroll
    for (int e = tid; e < 64 * 32; e += THREADS) {
        int dm = e >> 5, b = e & 31;
        int d = dm >> 2, m = dm & 3;
        float cc = centers[d * Mn + m];
        float ww = widths[d * Mn + m];
        float df = xs[b * Dn + d] - cc;
        mf[dm * 32 + b] = expf(-df * df / (2.f * ww * ww));
    }
    __syncthreads();

    // groups 0-3: 3 dims each, 64 entries
    for (int pp = w; pp < 256; pp += WARPS) {
        int g = pp >> 6, idx = pp & 63;
        tbl[pp * 32 + lane] =
            mf[((3*g + 0) * 4 + ( idx       & 3)) * 32 + lane] *
            mf[((3*g + 1) * 4 + ((idx >> 2) & 3)) * 32 + lane] *
            mf[((3*g + 2) * 4 + ( idx >> 4     )) * 32 + lane];
    }
    // pair tables for group 4 (dims 12-13, 14-15)
    for (int pp = w; pp < 32; pp += WARPS) {
        int grp = pp >> 4, i2 = pp & 15;
        int d0 = 12 + grp * 2;
        pair[pp * 32 + lane] =
            mf[(d0     * 4 + (i2 & 3))  * 32 + lane] *
            mf[((d0+1) * 4 + (i2 >> 2)) * 32 + lane];
    }
    __syncthreads();
    // group 4: 4 dims, 256 entries
    for (int pp = w; pp < 256; pp += WARPS) {
        tbl[(256 + pp) * 32 + lane] =
            pair[(pp & 15) * 32 + lane] * pair[(16 + (pp >> 4)) * 32 + lane];
    }
    __syncthreads();   // stage region free from here

    // ---- main loop: 128 rules/warp in chunks of 16, all-smem ----
    const char* tbB = (const char*)tbl + lane * 4;
    const ulonglong2* cs2 = (const ulonglong2*)csm;
    const int rbase = w * RPW;
    float* stg = stage + w * (CHUNK * SSTRIDE);

    unsigned long long a01 = 0, a23 = 0, a45 = 0, a67 = 0, a89 = 0, aSF = 0;

    for (int ch = 0; ch < RPW / CHUNK; ch++) {
        const int r0 = rbase + ch * CHUNK;
#pragma unroll 8
        for (int rl = 0; rl < CHUNK; rl++) {
            const int r = r0 + rl;
            const uint2 oa = sofA[r];                 // LDS.64 broadcast
            const uint32_t o4 = sofB[r];              // LDS.U16 broadcast
            float f0 = *(const float*)(tbB + (oa.x & 0xFFFFu));
            float f1 = *(const float*)(tbB + (oa.x >> 16));
            float f2 = *(const float*)(tbB + (oa.y & 0xFFFFu));
            float f3 = *(const float*)(tbB + (oa.y >> 16));
            float f4 = *(const float*)(tbB + o4);
            float f = ((f0 * f1) * (f2 * f3)) * f4;
            stg[rl * SSTRIDE + lane] = f;
            unsigned long long fp = bcast2(f);
            ulonglong2 v0 = cs2[r * 3 + 0];           // LDS.128 broadcast
            ulonglong2 v1 = cs2[r * 3 + 1];
            ulonglong2 v2 = cs2[r * 3 + 2];
            ffma2(a01, fp, v0.x); ffma2(a23, fp, v0.y);
            ffma2(a45, fp, v1.x); ffma2(a67, fp, v1.y);
            ffma2(a89, fp, v2.x); ffma2(aSF, fp, v2.y);   // .lo = fsum
        }
        __syncwarp();
        if (write_aux) {
            // transposed flush: 2 rows x 16 rules per pass, 64B stores
#pragma unroll
            for (int t2 = 0; t2 < 16; t2++) {
                int row = 2 * t2 + (lane >> 4);   // batch row 0..31
                int j = lane & 15;                // rule-in-chunk 0..15
                nf[(size_t)(b0 + row) * Rn + r0 + j] = stg[j * SSTRIDE + row];
            }
        }
        __syncwarp();
    }

    // ---- CTA reduction (smem atomics, one-time) ----
    {
        union { unsigned long long u; float2 f; } c0, c1, c2, c3, c4, c5;
        c0.u = a01; c1.u = a23; c2.u = a45; c3.u = a67; c4.u = a89; c5.u = aSF;
        atomicAdd(&red[ 0 * 32 + lane], c0.f.x);
        atomicAdd(&red[ 1 * 32 + lane], c0.f.y);
        atomicAdd(&red[ 2 * 32 + lane], c1.f.x);
        atomicAdd(&red[ 3 * 32 + lane], c1.f.y);
        atomicAdd(&red[ 4 * 32 + lane], c2.f.x);
        atomicAdd(&red[ 5 * 32 + lane], c2.f.y);
        atomicAdd(&red[ 6 * 32 + lane], c3.f.x);
        atomicAdd(&red[ 7 * 32 + lane], c3.f.y);
        atomicAdd(&red[ 8 * 32 + lane], c4.f.x);
        atomicAdd(&red[ 9 * 32 + lane], c4.f.y);
        atomicAdd(&red[10 * 32 + lane], c5.f.x);
    }
    __syncthreads();

    if (tid < 32)
        inv_s[tid] = 1.f / (red[10 * 32 + tid] + EPSV);
    __syncthreads();

    // out[b][c] = sx[b] * inv[b] * acc[b][c]
    if (tid < BT * Cn) {
        int b = tid & 31, c = tid >> 5;
        float s = 1.f;
#pragma unroll
        for (int d = 0; d < Dn; d++) s += xs[b * Dn + d];
        out[(size_t)(b0 + b) * Cn + c] = s * inv_s[b] * red[c * 32 + b];
    }

    if (write_aux) {
        // xext: 544 elements -> strided loop (THREADS=512 < 544!)
        for (int i = tid; i < BT * (Dn + 1); i += THREADS) {
            int b = i / (Dn + 1), j = i % (Dn + 1);
            xext[(size_t)(b0 + b) * (Dn + 1) + j] =
                (j < Dn) ? xs[b * Dn + j] : 1.f;
        }
        // in-place normalize of this CTA's nf region (L2-resident), float4
        __syncthreads();
        float4* p = (float4*)(nf + (size_t)b0 * Rn);
#pragma unroll
        for (int k = 0; k < 32; k++) {
            int i = tid + k * THREADS;          // 16384 float4 = 32 rows x 512
            float iv = inv_s[i >> 9];           // Rn/4 = 512 float4 per row
            float4 v = p[i];
            v.x *= iv; v.y *= iv; v.z *= iv; v.w *= iv;
            p[i] = v;
        }
    }
}

// ---------------------------------------------------------------------------
extern "C" void kernel_launch(void* const* d_in, const int* in_sizes, int n_in,
                              void* d_out, int out_size) {
    const float* x       = (const float*)d_in[0];
    const float* centers = (const float*)d_in[1];
    const float* widths  = (const float*)d_in[2];
    const float* cons    = (const float*)d_in[3];
    const int*   rules   = (const int*)d_in[4];

    float* out = (float*)d_out;
    const long total = (long)Bn * Cn + (long)Bn * Rn + (long)Bn * (Dn + 1);
    const int write_aux = (out_size >= total) ? 1 : 0;
    float* nf   = out + (size_t)Bn * Cn;
    float* xext = nf + (size_t)Bn * Rn;

    anfis_prep<<<Rn / 8, 256>>>(cons, rules);

    cudaFuncSetAttribute(anfis_main, cudaFuncAttributeMaxDynamicSharedMemorySize,
                         SMEM_BYTES);
    anfis_main<<<Bn / BT, THREADS, SMEM_BYTES>>>(x, centers, widths,
                                                 out, nf, xext, write_aux);
}